// round 4
// baseline (speedup 1.0000x reference)
#include <cuda_runtime.h>
#include <cuda_bf16.h>
#include <math.h>

// B=8, D=64, T=512, O=256 (fixed by the reference)
#define PB 8
#define PD 64
#define PT 512
#define PO 256
#define THREADS 64

typedef unsigned long long u64;

__device__ __forceinline__ float ex2a(float x) {
    float y; asm("ex2.approx.ftz.f32 %0, %1;" : "=f"(y) : "f"(x)); return y;
}
__device__ __forceinline__ float lg2a(float x) {
    float y; asm("lg2.approx.ftz.f32 %0, %1;" : "=f"(y) : "f"(x)); return y;
}
__device__ __forceinline__ u64 pk2(float lo, float hi) {
    u64 r; asm("mov.b64 %0, {%1, %2};" : "=l"(r) : "f"(lo), "f"(hi)); return r;
}
__device__ __forceinline__ void upk2(u64 v, float& lo, float& hi) {
    asm("mov.b64 {%0, %1}, %2;" : "=f"(lo), "=f"(hi) : "l"(v));
}
__device__ __forceinline__ u64 fma2(u64 a, u64 b, u64 c) {
    u64 d; asm("fma.rn.f32x2 %0, %1, %2, %3;" : "=l"(d) : "l"(a), "l"(b), "l"(c)); return d;
}
__device__ __forceinline__ u64 mul2(u64 a, u64 b) {
    u64 d; asm("mul.rn.f32x2 %0, %1, %2;" : "=l"(d) : "l"(a), "l"(b)); return d;
}
__device__ __forceinline__ u64 add2(u64 a, u64 b) {
    u64 d; asm("add.rn.f32x2 %0, %1, %2;" : "=l"(d) : "l"(a), "l"(b)); return d;
}

__global__ __launch_bounds__(THREADS, 8)
void interp_kernel(const float* __restrict__ x,
                   const float* __restrict__ grid,
                   const float* __restrict__ kern,
                   float* __restrict__ out) {
    // 1024 blocks: (b, d, half-of-o). 64 threads; each thread does 2 outputs.
    const int bid  = blockIdx.x;
    const int h    = bid & 1;
    const int d    = (bid >> 1) & (PD - 1);
    const int b    = bid >> 7;
    const int tid  = threadIdx.x;
    const int lane = tid & 31;
    const int wid  = tid >> 5;            // 0 or 1

    // Per-warp compacted segments (warp w owns t in [256w, 256w+256)).
    __shared__ __align__(16) float sA[PT];  // c1*t^2
    __shared__ __align__(16) float sB[PT];  // -2*c1*t
    __shared__ __align__(16) float sV[PT];  // vals
    __shared__ int scnt[2];

    const float* vp = x + (size_t)(b * 3 * PD + d) * PT;
    const float* mp = x + (size_t)(b * 3 * PD + PD + d) * PT;
    const float* tp = x + (size_t)(b * 3 * PD + 2 * PD + d) * PT;

    const float k = kern[d];
    const float alpha = (k > 20.0f) ? k : log1pf(__expf(k));
    const float c1 = -alpha * 1.4426950408889634f;   // -alpha*log2(e)

    // ---- Warp-private compaction: active points have m == 1 exactly ----
    {
        const int tbase = wid * 256;
        int cnt = 0;
        #pragma unroll
        for (int r = 0; r < 8; r++) {
            const int t = tbase + r * 32 + lane;
            const float mv = mp[t];
            const float tv = tp[t];
            const float vv = vp[t];
            const bool act = (mv > 0.5f);
            const unsigned bal = __ballot_sync(0xffffffffu, act);
            if (act) {
                const int idx = tbase + cnt + __popc(bal & ((1u << lane) - 1u));
                sA[idx] = c1 * tv * tv;
                sB[idx] = -2.0f * c1 * tv;
                sV[idx] = vv;
            }
            cnt += __popc(bal);
        }
        const int cpad = (cnt + 3) & ~3;   // multiple of 4, <= 256
        for (int i = cnt + lane; i < cpad; i += 32) {
            sA[tbase + i] = -160.0f;       // 2^-160 -> FTZ 0: zero weight
            sB[tbase + i] = 0.0f;
            sV[tbase + i] = 0.0f;
        }
        if (lane == 0) scnt[wid] = cpad;
    }
    __syncthreads();

    const int o0 = h * 128 + tid;
    const int o1 = o0 + THREADS;
    const float g0 = grid[b * PO + o0];
    const float g1 = grid[b * PO + o1];
    const u64 G0 = pk2(g0, g0);
    const u64 G1 = pk2(g1, g1);

    u64 aw1a = 0, ay1a = 0, aw2a = 0, ay2a = 0;   // output o0
    u64 aw1b = 0, ay1b = 0, aw2b = 0, ay2b = 0;   // output o1

    #pragma unroll
    for (int seg = 0; seg < 2; seg++) {
        const int base = seg * 256;
        const int ns = scnt[seg];
        for (int i = 0; i < ns; i += 4) {
            #pragma unroll
            for (int p = 0; p < 2; p++) {
                const int idx = base + i + 2 * p;
                const u64 Ap = *(const u64*)(sA + idx);   // packed point pair
                const u64 Bp = *(const u64*)(sB + idx);
                const u64 Vp = *(const u64*)(sV + idx);

                const u64 arg0 = fma2(Bp, G0, Ap);
                const u64 arg1 = fma2(Bp, G1, Ap);
                float x0, x1, x2, x3;
                upk2(arg0, x0, x1);
                upk2(arg1, x2, x3);
                const u64 Ea = pk2(ex2a(x0), ex2a(x1));
                const u64 Eb = pk2(ex2a(x2), ex2a(x3));

                // e^10 = ((e^2)^2)^2 * e^2  (mask==1 -> logm==0 exactly)
                const u64 a2 = mul2(Ea, Ea);
                const u64 a4 = mul2(a2, a2);
                const u64 a8 = mul2(a4, a4);
                const u64 Ea10 = mul2(a8, a2);
                const u64 b2 = mul2(Eb, Eb);
                const u64 b4 = mul2(b2, b2);
                const u64 b8 = mul2(b4, b4);
                const u64 Eb10 = mul2(b8, b2);

                aw1a = add2(aw1a, Ea);
                ay1a = fma2(Ea, Vp, ay1a);
                aw2a = add2(aw2a, Ea10);
                ay2a = fma2(Ea10, Vp, ay2a);
                aw1b = add2(aw1b, Eb);
                ay1b = fma2(Eb, Vp, ay1b);
                aw2b = add2(aw2b, Eb10);
                ay2b = fma2(Eb10, Vp, ay2b);
            }
        }
    }

    float* ob = out + (size_t)(b * 3 * PD) * PO;
    const float ln2 = 0.6931471805599453f;

    {
        float wl, wh, yl, yh, w2l, w2h, y2l, y2h;
        upk2(aw1a, wl, wh); upk2(ay1a, yl, yh);
        upk2(aw2a, w2l, w2h); upk2(ay2a, y2l, y2h);
        const float sw1 = wl + wh, sy1 = yl + yh;
        const float sw2 = w2l + w2h, sy2 = y2l + y2h;
        const float w = (lg2a(sw1) + c1 * g0 * g0) * ln2;
        ob[(size_t)(d) * PO + o0]          = __fdividef(sy1, sw1);
        ob[(size_t)(PD + d) * PO + o0]     = w;
        ob[(size_t)(2 * PD + d) * PO + o0] = __fdividef(sy2, sw2);
    }
    {
        float wl, wh, yl, yh, w2l, w2h, y2l, y2h;
        upk2(aw1b, wl, wh); upk2(ay1b, yl, yh);
        upk2(aw2b, w2l, w2h); upk2(ay2b, y2l, y2h);
        const float sw1 = wl + wh, sy1 = yl + yh;
        const float sw2 = w2l + w2h, sy2 = y2l + y2h;
        const float w = (lg2a(sw1) + c1 * g1 * g1) * ln2;
        ob[(size_t)(d) * PO + o1]          = __fdividef(sy1, sw1);
        ob[(size_t)(PD + d) * PO + o1]     = w;
        ob[(size_t)(2 * PD + d) * PO + o1] = __fdividef(sy2, sw2);
    }
}

extern "C" void kernel_launch(void* const* d_in, const int* in_sizes, int n_in,
                              void* d_out, int out_size) {
    const float* x    = (const float*)d_in[0];   // (8, 192, 512)
    const float* grid = (const float*)d_in[1];   // (8, 256)
    const float* kern = (const float*)d_in[2];   // (64,)
    float* out = (float*)d_out;                  // (8, 192, 256)

    interp_kernel<<<PB * PD * 2, THREADS>>>(x, grid, kern, out);
}